// round 8
// baseline (speedup 1.0000x reference)
#include <cuda_runtime.h>
#include <math.h>
#include <stdint.h>

#define Bb   32
#define Ss   256
#define Ee   768
#define Hh   512
#define Cc   30
#define IN0v 770
#define Gg   2048
#define SB   (Ss*Bb)          /* 8192 */
#define LSTRIDE (Bb*Ss*Ee)    /* hidden_states layer stride */
#define NCTA_DIR 64

// ---------------- scratch (device globals; no runtime allocation) ------------
__device__ float g_x0[SB*IN0v];        // [S][B][770]  layer-0 input features
__device__ float g_xw[2][SB*Gg];       // [dir][S][B][2048] precomputed input proj
__device__ float g_seq0[SB*1024];      // [S][B][1024] layer-0 output
__device__ float g_seq1[SB*1024];      // [S][B][1024] layer-1 output
__device__ float g_hT[2*2*Hh*Bb];      // [dir][parity][h][b] double-buffered h
__device__ float g_mw[Bb*Ss];          // mean over E per (b,s)
__device__ float g_mp[Bb];             // mean at predicate position per b
__device__ unsigned g_cnt[2];          // per-direction barrier arrive count
__device__ unsigned g_gen[2];          // per-direction barrier generation

// ---------------- feature build ----------------------------------------------
__global__ void feat_mean_kernel(const float* __restrict__ hs)
{
    int bs = blockIdx.x;              // b*Ss + s
    int b = bs / Ss, s = bs % Ss;
    const float* p = hs + ((size_t)b*Ss + s)*Ee;
    size_t xb = ((size_t)s*Bb + b)*IN0v;
    float lsum = 0.f;
    for (int e = threadIdx.x; e < Ee; e += 256){
        float v = (p[e] + p[e+LSTRIDE] + p[e+2*LSTRIDE] + p[e+3*LSTRIDE])*0.25f;
        g_x0[xb + e] = v;
        lsum += v;
    }
    __shared__ float sred[256];
    sred[threadIdx.x] = lsum;
    __syncthreads();
    for (int st = 128; st > 0; st >>= 1){
        if (threadIdx.x < st) sred[threadIdx.x] += sred[threadIdx.x + st];
        __syncthreads();
    }
    if (threadIdx.x == 0) g_mw[bs] = sred[0]*(1.f/768.f);
}

__global__ void pred_kernel(const int* __restrict__ pred)
{
    int b = threadIdx.x;
    if (b >= Bb) return;
    const int* row = pred + b*Ss;
    int best = row[0], idx = 0;
    for (int s = 1; s < Ss; s++){ int v = row[s]; if (v > best){ best = v; idx = s; } }
    g_mp[b] = g_mw[b*Ss + idx];
}

__global__ void fill_kernel(const int* __restrict__ roles)
{
    int t = blockIdx.x*blockDim.x + threadIdx.x;
    if (t >= Bb*Ss) return;
    int b = t / Ss, s = t % Ss;
    int r = roles[t];
    size_t xb = ((size_t)s*Bb + b)*IN0v;
    g_x0[xb + Ee]     = g_mw[t] - g_mp[b];
    g_x0[xb + Ee + 1] = (r != 0 && r != -100) ? 1.f : 0.f;
}

// ---------------- input-projection SGEMM  C = A * W^T + (b1+b2) --------------
// (exact R5-passing version)
__global__ __launch_bounds__(256) void sgemm_bias(
    int srcSel, const float* __restrict__ W,
    const float* __restrict__ b1, const float* __restrict__ b2,
    int dstDir, int K)
{
    const float* A = srcSel ? g_seq0 : g_x0;
    float* Cmat = g_xw[dstDir];
    const int N = Gg;
    __shared__ float As[8][128];
    __shared__ float Wsm[8][128];
    int m0 = blockIdx.y*128, n0 = blockIdx.x*128;
    int tid = threadIdx.x;
    int tx = tid & 15, ty = tid >> 4;
    float acc[8][8];
#pragma unroll
    for (int i=0;i<8;i++)
#pragma unroll
        for (int j=0;j<8;j++) acc[i][j] = 0.f;

    for (int k0 = 0; k0 < K; k0 += 8){
#pragma unroll
        for (int i = 0; i < 4; i++){
            int idx = tid + i*256;
            int kk = idx & 7, mm = idx >> 3;
            int gk = k0 + kk;
            float av = 0.f, wv = 0.f;
            if (gk < K){
                av = A[(size_t)(m0+mm)*K + gk];
                wv = W[(size_t)(n0+mm)*K + gk];
            }
            As[kk][mm] = av;
            Wsm[kk][mm] = wv;
        }
        __syncthreads();
#pragma unroll
        for (int kk = 0; kk < 8; kk++){
            float a[8], w[8];
#pragma unroll
            for (int i=0;i<8;i++) a[i] = As[kk][ty*8+i];
#pragma unroll
            for (int j=0;j<8;j++) w[j] = Wsm[kk][tx*8+j];
#pragma unroll
            for (int i=0;i<8;i++)
#pragma unroll
                for (int j=0;j<8;j++)
                    acc[i][j] = fmaf(a[i], w[j], acc[i][j]);
        }
        __syncthreads();
    }
#pragma unroll
    for (int i=0;i<8;i++){
        int m = m0 + ty*8 + i;
#pragma unroll
        for (int j=0;j<8;j++){
            int n = n0 + tx*8 + j;
            Cmat[(size_t)m*N + n] = acc[i][j] + b1[n] + b2[n];
        }
    }
}

// ---------------- persistent bidirectional LSTM layer ------------------------
__device__ __forceinline__ float sigf(float x){ return 1.f/(1.f + expf(-x)); }

__device__ __forceinline__ void grid_bar(int dir, unsigned* s_gen)
{
    __syncthreads();
    if (threadIdx.x == 0){
        __threadfence();
        unsigned g0 = *s_gen;
        if (atomicAdd(&g_cnt[dir], 1u) == NCTA_DIR - 1u){
            g_cnt[dir] = 0u;
            __threadfence();
            atomicAdd(&g_gen[dir], 1u);
        } else {
            while (atomicAdd(&g_gen[dir], 0u) == g0) { __nanosleep(64); }
        }
        __threadfence();
        *s_gen = g0 + 1u;
    }
    __syncthreads();
}

// grid = 128 CTAs (64 per direction), 256 threads, dynamic smem 147968 B.
__global__ __launch_bounds__(256,1) void lstm_layer_kernel(
    const float* __restrict__ Whh_f, const float* __restrict__ Whh_b, int layer)
{
    extern __shared__ float sm[];
    float* W_s  = sm;                    // [512][32] transposed Whh slice  (64KB)
    float* hp_s = sm + 512*32;           // [512][32] h_prev transposed     (64KB)
    float* red  = sm + 2*512*32;         // [4][32][33] partials/gates
    __shared__ unsigned s_gen;

    int dir = blockIdx.x >> 6;
    int cid = blockIdx.x & 63;
    int hc0 = cid * 8;
    int tid = threadIdx.x;
    const float* Whh = dir ? Whh_b : Whh_f;
    const float* xw  = g_xw[dir];
    float* outseq = layer ? g_seq1 : g_seq0;

    if (tid == 0) s_gen = g_gen[dir];

    // Load Whh slice transposed: W_s[k][q*8+j] = Whh[q*512 + hc0 + j][k]
    for (int idx = tid; idx < 512*32; idx += 256){
        int col = idx & 31, k = idx >> 5;
        int q = col >> 3, j = col & 7;
        W_s[k*32 + col] = Whh[(size_t)(q*512 + hc0 + j)*512 + k];
    }
    // Zero parity-0 h buffer for the columns this CTA owns
    {
        int j = tid >> 5, b = tid & 31;
        g_hT[(dir*2 + 0)*Hh*Bb + (hc0+j)*Bb + b] = 0.f;
    }
    float c_reg = 0.f;
    int jj = tid >> 5, bbn = tid & 31;

    int kg = tid >> 6;                   // k-split group
    int t2 = tid & 63;
    int bq = (t2 & 7) * 4;
    int gq = (t2 >> 3) * 4;

    // xw addressing: same mapping as the R4 reduction loop (idx = tid + 256*r)
    int colp = tid & 31;
    int xoff = (colp >> 3)*512 + hc0 + (colp & 7);
    int bI0  = tid >> 5;

    grid_bar(dir, &s_gen);

    for (int t = 0; t < Ss; t++){
        int s = dir ? (Ss - 1 - t) : t;
        const float* xwt = xw + (size_t)s*Bb*Gg;

        // prefetch input-projection gate values (latency hidden behind matmul)
        float xpre[4];
#pragma unroll
        for (int r = 0; r < 4; r++)
            xpre[r] = __ldg(&xwt[(size_t)(bI0 + 8*r)*Gg + xoff]);

        // stage h_prev into smem (vectorized: 16 float4 per thread)
        const float4* hsrc4 = (const float4*)(g_hT + (dir*2 + (t & 1))*Hh*Bb);
        float4* hp4 = (float4*)hp_s;
#pragma unroll
        for (int r = 0; r < 16; r++)
            hp4[tid + 256*r] = hsrc4[tid + 256*r];
        __syncthreads();

        float acc[4][4];
#pragma unroll
        for (int i=0;i<4;i++)
#pragma unroll
            for (int j=0;j<4;j++) acc[i][j] = 0.f;

        const float* hpk = hp_s + kg*128*32;
        const float* wpk = W_s  + kg*128*32;
#pragma unroll 8
        for (int k = 0; k < 128; k++){
            float4 hv = *reinterpret_cast<const float4*>(hpk + (k<<5) + bq);
            float4 wv = *reinterpret_cast<const float4*>(wpk + (k<<5) + gq);
            acc[0][0]=fmaf(wv.x,hv.x,acc[0][0]); acc[0][1]=fmaf(wv.x,hv.y,acc[0][1]);
            acc[0][2]=fmaf(wv.x,hv.z,acc[0][2]); acc[0][3]=fmaf(wv.x,hv.w,acc[0][3]);
            acc[1][0]=fmaf(wv.y,hv.x,acc[1][0]); acc[1][1]=fmaf(wv.y,hv.y,acc[1][1]);
            acc[1][2]=fmaf(wv.y,hv.z,acc[1][2]); acc[1][3]=fmaf(wv.y,hv.w,acc[1][3]);
            acc[2][0]=fmaf(wv.z,hv.x,acc[2][0]); acc[2][1]=fmaf(wv.z,hv.y,acc[2][1]);
            acc[2][2]=fmaf(wv.z,hv.z,acc[2][2]); acc[2][3]=fmaf(wv.z,hv.w,acc[2][3]);
            acc[3][0]=fmaf(wv.w,hv.x,acc[3][0]); acc[3][1]=fmaf(wv.w,hv.y,acc[3][1]);
            acc[3][2]=fmaf(wv.w,hv.z,acc[3][2]); acc[3][3]=fmaf(wv.w,hv.w,acc[3][3]);
        }
#pragma unroll
        for (int gi=0; gi<4; gi++)
#pragma unroll
            for (int bi=0; bi<4; bi++)
                red[kg*1056 + (gq+gi)*33 + (bq+bi)] = acc[gi][bi];
        __syncthreads();

        // reduce k-splits + add prefetched input projection
#pragma unroll
        for (int r = 0; r < 4; r++){
            int bI = bI0 + 8*r;
            float v = red[colp*33 + bI] + red[1056 + colp*33 + bI]
                    + red[2112 + colp*33 + bI] + red[3168 + colp*33 + bI]
                    + xpre[r];
            red[colp*33 + bI] = v;
        }
        __syncthreads();

        // activations + state update (gate cols: i=j, f=8+j, g=16+j, o=24+j)
        float iv = red[( 0 + jj)*33 + bbn];
        float fv = red[( 8 + jj)*33 + bbn];
        float gv = red[(16 + jj)*33 + bbn];
        float ov = red[(24 + jj)*33 + bbn];
        float cnew = sigf(fv)*c_reg + sigf(iv)*tanhf(gv);
        float hnew = sigf(ov)*tanhf(cnew);
        c_reg = cnew;
        g_hT[(dir*2 + ((t+1)&1))*Hh*Bb + (hc0+jj)*Bb + bbn] = hnew;
        outseq[((size_t)s*Bb + bbn)*1024 + dir*512 + hc0 + jj] = hnew;

        grid_bar(dir, &s_gen);
    }
}

// ---------------- output projection [8192,1024] x [1024,30] ------------------
__global__ void out_proj_kernel(const float* __restrict__ Wout,
                                const float* __restrict__ bout,
                                float* __restrict__ out)
{
    int gw = (blockIdx.x*blockDim.x + threadIdx.x) >> 5;
    int lane = threadIdx.x & 31;
    if (gw >= SB) return;
    const float* row = g_seq1 + (size_t)gw*1024;
    float xv[32];
#pragma unroll
    for (int i=0;i<32;i++) xv[i] = row[lane + 32*i];
    int s = gw >> 5, b = gw & 31;
    float* orow = out + ((size_t)b*Ss + s)*Cc;
    for (int c = 0; c < Cc; c++){
        const float* w = Wout + c*1024;
        float acc = 0.f;
#pragma unroll
        for (int i=0;i<32;i++) acc = fmaf(xv[i], w[lane + 32*i], acc);
#pragma unroll
        for (int off=16; off; off>>=1) acc += __shfl_xor_sync(0xffffffffu, acc, off);
        if (lane == 0) orow[c] = acc + bout[c];
    }
}

// ---------------- launch ------------------------------------------------------
extern "C" void kernel_launch(void* const* d_in, const int* in_sizes, int n_in,
                              void* d_out, int out_size)
{
    const float* hs     = (const float*)d_in[0];
    const int*   roles  = (const int*)  d_in[1];
    const int*   preds  = (const int*)  d_in[2];
    const float* Wih0f  = (const float*)d_in[3];
    const float* Whh0f  = (const float*)d_in[4];
    const float* bih0f  = (const float*)d_in[5];
    const float* bhh0f  = (const float*)d_in[6];
    const float* Wih0b  = (const float*)d_in[7];
    const float* Whh0b  = (const float*)d_in[8];
    const float* bih0b  = (const float*)d_in[9];
    const float* bhh0b  = (const float*)d_in[10];
    const float* Wih1f  = (const float*)d_in[11];
    const float* Whh1f  = (const float*)d_in[12];
    const float* bih1f  = (const float*)d_in[13];
    const float* bhh1f  = (const float*)d_in[14];
    const float* Wih1b  = (const float*)d_in[15];
    const float* Whh1b  = (const float*)d_in[16];
    const float* bih1b  = (const float*)d_in[17];
    const float* bhh1b  = (const float*)d_in[18];
    const float* Wout   = (const float*)d_in[19];
    const float* bout   = (const float*)d_in[20];
    float* out = (float*)d_out;

    const size_t lsm = (2*512*32 + 4*1056) * sizeof(float);   // 147968
    cudaFuncSetAttribute(lstm_layer_kernel,
                         cudaFuncAttributeMaxDynamicSharedMemorySize, (int)lsm);

    feat_mean_kernel<<<SB, 256>>>(hs);
    pred_kernel<<<1, 32>>>(preds);
    fill_kernel<<<(Bb*Ss + 255)/256, 256>>>(roles);

    dim3 gproj(Gg/128, SB/128);
    sgemm_bias<<<gproj, 256>>>(0, Wih0f, bih0f, bhh0f, 0, IN0v);
    sgemm_bias<<<gproj, 256>>>(0, Wih0b, bih0b, bhh0b, 1, IN0v);
    lstm_layer_kernel<<<128, 256, lsm>>>(Whh0f, Whh0b, 0);

    sgemm_bias<<<gproj, 256>>>(1, Wih1f, bih1f, bhh1f, 0, 1024);
    sgemm_bias<<<gproj, 256>>>(1, Wih1b, bih1b, bhh1b, 1, 1024);
    lstm_layer_kernel<<<128, 256, lsm>>>(Whh1f, Whh1b, 1);

    out_proj_kernel<<<(SB*32 + 255)/256, 256>>>(Wout, bout, out);
}

// round 9
// speedup vs baseline: 1.2117x; 1.2117x over previous
#include <cuda_runtime.h>
#include <math.h>
#include <stdint.h>

#define Bb   32
#define Ss   256
#define Ee   768
#define Hh   512
#define Cc   30
#define IN0v 770
#define Gg   2048
#define SB   (Ss*Bb)          /* 8192 */
#define LSTRIDE (Bb*Ss*Ee)    /* hidden_states layer stride */
#define NCTA_DIR 64

// ---------------- scratch (device globals; no runtime allocation) ------------
__device__ float g_x0[SB*IN0v];        // [S][B][770]  layer-0 input features
__device__ float g_xw[2][SB*Gg];       // [dir][S][B][2048] precomputed input proj
__device__ float g_seq0[SB*1024];      // [S][B][1024] layer-0 output
__device__ float g_seq1[SB*1024];      // [S][B][1024] layer-1 output
__device__ float g_hT[2*2*Hh*Bb];      // [dir][parity][h][b] double-buffered h
__device__ float g_mw[Bb*Ss];          // mean over E per (b,s)
__device__ float g_mp[Bb];             // mean at predicate position per b
__device__ unsigned g_cnt[2];          // per-direction barrier arrive count
__device__ unsigned g_gen[2];          // per-direction barrier generation

// ---------------- feature build ----------------------------------------------
__global__ void feat_mean_kernel(const float* __restrict__ hs)
{
    int bs = blockIdx.x;              // b*Ss + s
    int b = bs / Ss, s = bs % Ss;
    const float* p = hs + ((size_t)b*Ss + s)*Ee;
    size_t xb = ((size_t)s*Bb + b)*IN0v;
    float lsum = 0.f;
    for (int e = threadIdx.x; e < Ee; e += 256){
        float v = (p[e] + p[e+LSTRIDE] + p[e+2*LSTRIDE] + p[e+3*LSTRIDE])*0.25f;
        g_x0[xb + e] = v;
        lsum += v;
    }
    __shared__ float sred[256];
    sred[threadIdx.x] = lsum;
    __syncthreads();
    for (int st = 128; st > 0; st >>= 1){
        if (threadIdx.x < st) sred[threadIdx.x] += sred[threadIdx.x + st];
        __syncthreads();
    }
    if (threadIdx.x == 0) g_mw[bs] = sred[0]*(1.f/768.f);
}

__global__ void pred_kernel(const int* __restrict__ pred)
{
    int b = threadIdx.x;
    if (b >= Bb) return;
    const int* row = pred + b*Ss;
    int best = row[0], idx = 0;
    for (int s = 1; s < Ss; s++){ int v = row[s]; if (v > best){ best = v; idx = s; } }
    g_mp[b] = g_mw[b*Ss + idx];
}

__global__ void fill_kernel(const int* __restrict__ roles)
{
    int t = blockIdx.x*blockDim.x + threadIdx.x;
    if (t >= Bb*Ss) return;
    int b = t / Ss, s = t % Ss;
    int r = roles[t];
    size_t xb = ((size_t)s*Bb + b)*IN0v;
    g_x0[xb + Ee]     = g_mw[t] - g_mp[b];
    g_x0[xb + Ee + 1] = (r != 0 && r != -100) ? 1.f : 0.f;
}

// ---------------- input-projection SGEMM  C = A * W^T + (b1+b2) --------------
// R5 skeleton (identical load mapping, compute order, K-guard, epilogue) with
// double-buffered SMEM + register staging: one __syncthreads per k-panel and
// global loads overlapped with FMA on the other buffer.
__global__ __launch_bounds__(256,2) void sgemm_bias(
    int srcSel, const float* __restrict__ W,
    const float* __restrict__ b1, const float* __restrict__ b2,
    int dstDir, int K)
{
    const float* A = srcSel ? g_seq0 : g_x0;
    float* Cmat = g_xw[dstDir];
    const int N = Gg;
    __shared__ float As[2][8][128];
    __shared__ float Wsm[2][8][128];
    int m0 = blockIdx.y*128, n0 = blockIdx.x*128;
    int tid = threadIdx.x;
    int tx = tid & 15, ty = tid >> 4;

    // R5's exact per-thread load slots: idx = tid + i*256
    int kkof[4], mmof[4];
#pragma unroll
    for (int i=0;i<4;i++){ int idx = tid + i*256; kkof[i] = idx & 7; mmof[i] = idx >> 3; }

    float acc[8][8];
#pragma unroll
    for (int i=0;i<8;i++)
#pragma unroll
        for (int j=0;j<8;j++) acc[i][j] = 0.f;

    float pa[4], pw[4];
    // prime panel k0=0 into registers, then buffer 0
#pragma unroll
    for (int i=0;i<4;i++){
        int gk = kkof[i];
        float av = 0.f, wv = 0.f;
        if (gk < K){
            av = A[(size_t)(m0+mmof[i])*K + gk];
            wv = W[(size_t)(n0+mmof[i])*K + gk];
        }
        pa[i] = av; pw[i] = wv;
    }
#pragma unroll
    for (int i=0;i<4;i++){
        As [0][kkof[i]][mmof[i]] = pa[i];
        Wsm[0][kkof[i]][mmof[i]] = pw[i];
    }
    __syncthreads();

    int buf = 0;
    for (int k0 = 0; k0 < K; k0 += 8){
        int has_next = (k0 + 8 < K);
        if (has_next){
#pragma unroll
            for (int i=0;i<4;i++){
                int gk = k0 + 8 + kkof[i];
                float av = 0.f, wv = 0.f;
                if (gk < K){
                    av = A[(size_t)(m0+mmof[i])*K + gk];
                    wv = W[(size_t)(n0+mmof[i])*K + gk];
                }
                pa[i] = av; pw[i] = wv;
            }
        }
#pragma unroll
        for (int kk = 0; kk < 8; kk++){
            float a[8], w[8];
#pragma unroll
            for (int i=0;i<8;i++) a[i] = As[buf][kk][ty*8+i];
#pragma unroll
            for (int j=0;j<8;j++) w[j] = Wsm[buf][kk][tx*8+j];
#pragma unroll
            for (int i=0;i<8;i++)
#pragma unroll
                for (int j=0;j<8;j++)
                    acc[i][j] = fmaf(a[i], w[j], acc[i][j]);
        }
        if (has_next){
#pragma unroll
            for (int i=0;i<4;i++){
                As [buf^1][kkof[i]][mmof[i]] = pa[i];
                Wsm[buf^1][kkof[i]][mmof[i]] = pw[i];
            }
            __syncthreads();
            buf ^= 1;
        }
    }
#pragma unroll
    for (int i=0;i<8;i++){
        int m = m0 + ty*8 + i;
#pragma unroll
        for (int j=0;j<8;j++){
            int n = n0 + tx*8 + j;
            Cmat[(size_t)m*N + n] = acc[i][j] + b1[n] + b2[n];
        }
    }
}

// ---------------- persistent bidirectional LSTM layer ------------------------
// (byte-for-byte the R5-measured version: 10,306 us total)
__device__ __forceinline__ float sigf(float x){ return 1.f/(1.f + expf(-x)); }

__device__ __forceinline__ void grid_bar(int dir, unsigned* s_gen)
{
    __syncthreads();
    if (threadIdx.x == 0){
        __threadfence();
        unsigned g0 = *s_gen;
        if (atomicAdd(&g_cnt[dir], 1u) == NCTA_DIR - 1u){
            g_cnt[dir] = 0u;
            __threadfence();
            atomicAdd(&g_gen[dir], 1u);
        } else {
            while (atomicAdd(&g_gen[dir], 0u) == g0) { __nanosleep(64); }
        }
        __threadfence();
        *s_gen = g0 + 1u;
    }
    __syncthreads();
}

// grid = 128 CTAs (64 per direction), 256 threads, dynamic smem 147968 B.
__global__ __launch_bounds__(256,1) void lstm_layer_kernel(
    const float* __restrict__ Whh_f, const float* __restrict__ Whh_b, int layer)
{
    extern __shared__ float sm[];
    float* W_s  = sm;                    // [512][32] transposed Whh slice  (64KB)
    float* hp_s = sm + 512*32;           // [512][32] h_prev transposed     (64KB)
    float* red  = sm + 2*512*32;         // [4][32][33] partials/gates      (~16.5KB)
    __shared__ unsigned s_gen;

    int dir = blockIdx.x >> 6;
    int cid = blockIdx.x & 63;
    int hc0 = cid * 8;
    int tid = threadIdx.x;
    const float* Whh = dir ? Whh_b : Whh_f;
    const float* xw  = g_xw[dir];
    float* outseq = layer ? g_seq1 : g_seq0;

    if (tid == 0) s_gen = g_gen[dir];

    // Load Whh slice transposed: W_s[k][q*8+j] = Whh[q*512 + hc0 + j][k]
    for (int idx = tid; idx < 512*32; idx += 256){
        int col = idx & 31, k = idx >> 5;
        int q = col >> 3, j = col & 7;
        W_s[k*32 + col] = Whh[(size_t)(q*512 + hc0 + j)*512 + k];
    }
    // Zero parity-0 h buffer for the columns this CTA owns
    {
        int j = tid >> 5, b = tid & 31;
        g_hT[(dir*2 + 0)*Hh*Bb + (hc0+j)*Bb + b] = 0.f;
    }
    float c_reg = 0.f;                   // cell state: thread (jj,bb) owns c[hc0+jj][bb]
    int jj = tid >> 5, bbn = tid & 31;

    int kg = tid >> 6;                   // k-split group (4 groups of 128 k each)
    int t2 = tid & 63;
    int bq = (t2 & 7) * 4;               // batch quad
    int gq = (t2 >> 3) * 4;              // gate-col quad

    grid_bar(dir, &s_gen);

    for (int t = 0; t < Ss; t++){
        int s = dir ? (Ss - 1 - t) : t;
        const float* hsrc = g_hT + (dir*2 + (t & 1))*Hh*Bb;
        for (int idx = tid; idx < 512*32; idx += 256)
            hp_s[idx] = hsrc[idx];
        __syncthreads();

        float acc[4][4];
#pragma unroll
        for (int i=0;i<4;i++)
#pragma unroll
            for (int j=0;j<4;j++) acc[i][j] = 0.f;

        const float* hpk = hp_s + kg*128*32;
        const float* wpk = W_s  + kg*128*32;
#pragma unroll 8
        for (int k = 0; k < 128; k++){
            float4 hv = *reinterpret_cast<const float4*>(hpk + (k<<5) + bq);
            float4 wv = *reinterpret_cast<const float4*>(wpk + (k<<5) + gq);
            acc[0][0]=fmaf(wv.x,hv.x,acc[0][0]); acc[0][1]=fmaf(wv.x,hv.y,acc[0][1]);
            acc[0][2]=fmaf(wv.x,hv.z,acc[0][2]); acc[0][3]=fmaf(wv.x,hv.w,acc[0][3]);
            acc[1][0]=fmaf(wv.y,hv.x,acc[1][0]); acc[1][1]=fmaf(wv.y,hv.y,acc[1][1]);
            acc[1][2]=fmaf(wv.y,hv.z,acc[1][2]); acc[1][3]=fmaf(wv.y,hv.w,acc[1][3]);
            acc[2][0]=fmaf(wv.z,hv.x,acc[2][0]); acc[2][1]=fmaf(wv.z,hv.y,acc[2][1]);
            acc[2][2]=fmaf(wv.z,hv.z,acc[2][2]); acc[2][3]=fmaf(wv.z,hv.w,acc[2][3]);
            acc[3][0]=fmaf(wv.w,hv.x,acc[3][0]); acc[3][1]=fmaf(wv.w,hv.y,acc[3][1]);
            acc[3][2]=fmaf(wv.w,hv.z,acc[3][2]); acc[3][3]=fmaf(wv.w,hv.w,acc[3][3]);
        }
#pragma unroll
        for (int gi=0; gi<4; gi++)
#pragma unroll
            for (int bi=0; bi<4; bi++)
                red[kg*1056 + (gq+gi)*33 + (bq+bi)] = acc[gi][bi];
        __syncthreads();

        // reduce k-splits + add precomputed input projection -> gate preacts
        const float* xwt = xw + (size_t)s*Bb*Gg;
#pragma unroll
        for (int idx = tid; idx < 1024; idx += 256){
            int bI = idx >> 5, col = idx & 31;
            int q = col >> 3, j2 = col & 7;
            float v = red[col*33 + bI] + red[1056 + col*33 + bI]
                    + red[2112 + col*33 + bI] + red[3168 + col*33 + bI];
            v += xwt[(size_t)bI*Gg + q*512 + hc0 + j2];
            red[col*33 + bI] = v;
        }
        __syncthreads();

        // activations + state update (gate cols: i=j, f=8+j, g=16+j, o=24+j)
        float iv = red[( 0 + jj)*33 + bbn];
        float fv = red[( 8 + jj)*33 + bbn];
        float gv = red[(16 + jj)*33 + bbn];
        float ov = red[(24 + jj)*33 + bbn];
        float cnew = sigf(fv)*c_reg + sigf(iv)*tanhf(gv);
        float hnew = sigf(ov)*tanhf(cnew);
        c_reg = cnew;
        g_hT[(dir*2 + ((t+1)&1))*Hh*Bb + (hc0+jj)*Bb + bbn] = hnew;
        outseq[((size_t)s*Bb + bbn)*1024 + dir*512 + hc0 + jj] = hnew;

        grid_bar(dir, &s_gen);
    }
}

// ---------------- output projection [8192,1024] x [1024,30] ------------------
__global__ void out_proj_kernel(const float* __restrict__ Wout,
                                const float* __restrict__ bout,
                                float* __restrict__ out)
{
    int gw = (blockIdx.x*blockDim.x + threadIdx.x) >> 5;   // one warp per (s,b)
    int lane = threadIdx.x & 31;
    if (gw >= SB) return;
    const float* row = g_seq1 + (size_t)gw*1024;
    float xv[32];
#pragma unroll
    for (int i=0;i<32;i++) xv[i] = row[lane + 32*i];
    int s = gw >> 5, b = gw & 31;
    float* orow = out + ((size_t)b*Ss + s)*Cc;
    for (int c = 0; c < Cc; c++){
        const float* w = Wout + c*1024;
        float acc = 0.f;
#pragma unroll
        for (int i=0;i<32;i++) acc = fmaf(xv[i], w[lane + 32*i], acc);
#pragma unroll
        for (int off=16; off; off>>=1) acc += __shfl_xor_sync(0xffffffffu, acc, off);
        if (lane == 0) orow[c] = acc + bout[c];
    }
}

// ---------------- launch ------------------------------------------------------
extern "C" void kernel_launch(void* const* d_in, const int* in_sizes, int n_in,
                              void* d_out, int out_size)
{
    const float* hs     = (const float*)d_in[0];
    const int*   roles  = (const int*)  d_in[1];
    const int*   preds  = (const int*)  d_in[2];
    const float* Wih0f  = (const float*)d_in[3];
    const float* Whh0f  = (const float*)d_in[4];
    const float* bih0f  = (const float*)d_in[5];
    const float* bhh0f  = (const float*)d_in[6];
    const float* Wih0b  = (const float*)d_in[7];
    const float* Whh0b  = (const float*)d_in[8];
    const float* bih0b  = (const float*)d_in[9];
    const float* bhh0b  = (const float*)d_in[10];
    const float* Wih1f  = (const float*)d_in[11];
    const float* Whh1f  = (const float*)d_in[12];
    const float* bih1f  = (const float*)d_in[13];
    const float* bhh1f  = (const float*)d_in[14];
    const float* Wih1b  = (const float*)d_in[15];
    const float* Whh1b  = (const float*)d_in[16];
    const float* bih1b  = (const float*)d_in[17];
    const float* bhh1b  = (const float*)d_in[18];
    const float* Wout   = (const float*)d_in[19];
    const float* bout   = (const float*)d_in[20];
    float* out = (float*)d_out;

    const size_t lsm = (2*512*32 + 4*1056) * sizeof(float);   // 147968
    cudaFuncSetAttribute(lstm_layer_kernel,
                         cudaFuncAttributeMaxDynamicSharedMemorySize, (int)lsm);

    feat_mean_kernel<<<SB, 256>>>(hs);
    pred_kernel<<<1, 32>>>(preds);
    fill_kernel<<<(Bb*Ss + 255)/256, 256>>>(roles);

    dim3 gproj(Gg/128, SB/128);
    sgemm_bias<<<gproj, 256>>>(0, Wih0f, bih0f, bhh0f, 0, IN0v);
    sgemm_bias<<<gproj, 256>>>(0, Wih0b, bih0b, bhh0b, 1, IN0v);
    lstm_layer_kernel<<<128, 256, lsm>>>(Whh0f, Whh0b, 0);

    sgemm_bias<<<gproj, 256>>>(1, Wih1f, bih1f, bhh1f, 0, 1024);
    sgemm_bias<<<gproj, 256>>>(1, Wih1b, bih1b, bhh1b, 1, 1024);
    lstm_layer_kernel<<<128, 256, lsm>>>(Whh1f, Whh1b, 1);

    out_proj_kernel<<<(SB*32 + 255)/256, 256>>>(Wout, bout, out);
}

// round 10
// speedup vs baseline: 1.4818x; 1.2229x over previous
#include <cuda_runtime.h>
#include <math.h>
#include <stdint.h>

#define Bb   32
#define Ss   256
#define Ee   768
#define Hh   512
#define Cc   30
#define IN0v 770
#define Gg   2048
#define SB   (Ss*Bb)          /* 8192 */
#define LSTRIDE (Bb*Ss*Ee)    /* hidden_states layer stride */
#define NCTA_DIR 128

// ---------------- scratch (device globals; no runtime allocation) ------------
__device__ float g_x0[SB*IN0v];        // [S][B][770]  layer-0 input features
__device__ float g_xw[2][SB*Gg];       // [dir][S][B][2048] precomputed input proj
__device__ float g_seq0[SB*1024];      // [S][B][1024] layer-0 output
__device__ float g_seq1[SB*1024];      // [S][B][1024] layer-1 output
__device__ float g_hT[2*2*Hh*Bb];      // [dir][parity][h][b] double-buffered h
__device__ float g_mw[Bb*Ss];          // mean over E per (b,s)
__device__ float g_mp[Bb];             // mean at predicate position per b
__device__ unsigned g_cnt[2];          // per-direction barrier arrive count
__device__ unsigned g_gen[2];          // per-direction barrier generation

// ---------------- feature build ----------------------------------------------
__global__ void feat_mean_kernel(const float* __restrict__ hs)
{
    int bs = blockIdx.x;              // b*Ss + s
    int b = bs / Ss, s = bs % Ss;
    const float* p = hs + ((size_t)b*Ss + s)*Ee;
    size_t xb = ((size_t)s*Bb + b)*IN0v;
    float lsum = 0.f;
    for (int e = threadIdx.x; e < Ee; e += 256){
        float v = (p[e] + p[e+LSTRIDE] + p[e+2*LSTRIDE] + p[e+3*LSTRIDE])*0.25f;
        g_x0[xb + e] = v;
        lsum += v;
    }
    __shared__ float sred[256];
    sred[threadIdx.x] = lsum;
    __syncthreads();
    for (int st = 128; st > 0; st >>= 1){
        if (threadIdx.x < st) sred[threadIdx.x] += sred[threadIdx.x + st];
        __syncthreads();
    }
    if (threadIdx.x == 0) g_mw[bs] = sred[0]*(1.f/768.f);
}

__global__ void pred_kernel(const int* __restrict__ pred)
{
    int b = threadIdx.x;
    if (b >= Bb) return;
    const int* row = pred + b*Ss;
    int best = row[0], idx = 0;
    for (int s = 1; s < Ss; s++){ int v = row[s]; if (v > best){ best = v; idx = s; } }
    g_mp[b] = g_mw[b*Ss + idx];
}

__global__ void fill_kernel(const int* __restrict__ roles)
{
    int t = blockIdx.x*blockDim.x + threadIdx.x;
    if (t >= Bb*Ss) return;
    int b = t / Ss, s = t % Ss;
    int r = roles[t];
    size_t xb = ((size_t)s*Bb + b)*IN0v;
    g_x0[xb + Ee]     = g_mw[t] - g_mp[b];
    g_x0[xb + Ee + 1] = (r != 0 && r != -100) ? 1.f : 0.f;
}

// ---------------- input-projection SGEMM  C = A * W^T + (b1+b2) --------------
// (R9-passing version, unchanged)
__global__ __launch_bounds__(256,2) void sgemm_bias(
    int srcSel, const float* __restrict__ W,
    const float* __restrict__ b1, const float* __restrict__ b2,
    int dstDir, int K)
{
    const float* A = srcSel ? g_seq0 : g_x0;
    float* Cmat = g_xw[dstDir];
    const int N = Gg;
    __shared__ float As[2][8][128];
    __shared__ float Wsm[2][8][128];
    int m0 = blockIdx.y*128, n0 = blockIdx.x*128;
    int tid = threadIdx.x;
    int tx = tid & 15, ty = tid >> 4;

    int kkof[4], mmof[4];
#pragma unroll
    for (int i=0;i<4;i++){ int idx = tid + i*256; kkof[i] = idx & 7; mmof[i] = idx >> 3; }

    float acc[8][8];
#pragma unroll
    for (int i=0;i<8;i++)
#pragma unroll
        for (int j=0;j<8;j++) acc[i][j] = 0.f;

    float pa[4], pw[4];
#pragma unroll
    for (int i=0;i<4;i++){
        int gk = kkof[i];
        float av = 0.f, wv = 0.f;
        if (gk < K){
            av = A[(size_t)(m0+mmof[i])*K + gk];
            wv = W[(size_t)(n0+mmof[i])*K + gk];
        }
        pa[i] = av; pw[i] = wv;
    }
#pragma unroll
    for (int i=0;i<4;i++){
        As [0][kkof[i]][mmof[i]] = pa[i];
        Wsm[0][kkof[i]][mmof[i]] = pw[i];
    }
    __syncthreads();

    int buf = 0;
    for (int k0 = 0; k0 < K; k0 += 8){
        int has_next = (k0 + 8 < K);
        if (has_next){
#pragma unroll
            for (int i=0;i<4;i++){
                int gk = k0 + 8 + kkof[i];
                float av = 0.f, wv = 0.f;
                if (gk < K){
                    av = A[(size_t)(m0+mmof[i])*K + gk];
                    wv = W[(size_t)(n0+mmof[i])*K + gk];
                }
                pa[i] = av; pw[i] = wv;
            }
        }
#pragma unroll
        for (int kk = 0; kk < 8; kk++){
            float a[8], w[8];
#pragma unroll
            for (int i=0;i<8;i++) a[i] = As[buf][kk][ty*8+i];
#pragma unroll
            for (int j=0;j<8;j++) w[j] = Wsm[buf][kk][tx*8+j];
#pragma unroll
            for (int i=0;i<8;i++)
#pragma unroll
                for (int j=0;j<8;j++)
                    acc[i][j] = fmaf(a[i], w[j], acc[i][j]);
        }
        if (has_next){
#pragma unroll
            for (int i=0;i<4;i++){
                As [buf^1][kkof[i]][mmof[i]] = pa[i];
                Wsm[buf^1][kkof[i]][mmof[i]] = pw[i];
            }
            __syncthreads();
            buf ^= 1;
        }
    }
#pragma unroll
    for (int i=0;i<8;i++){
        int m = m0 + ty*8 + i;
#pragma unroll
        for (int j=0;j<8;j++){
            int n = n0 + tx*8 + j;
            Cmat[(size_t)m*N + n] = acc[i][j] + b1[n] + b2[n];
        }
    }
}

// ---------------- persistent bidirectional LSTM layer ------------------------
__device__ __forceinline__ float sigf(float x){ return 1.f/(1.f + expf(-x)); }

__device__ __forceinline__ void grid_bar(int dir, unsigned* s_gen)
{
    __syncthreads();
    if (threadIdx.x == 0){
        __threadfence();
        unsigned g0 = *s_gen;
        if (atomicAdd(&g_cnt[dir], 1u) == NCTA_DIR - 1u){
            g_cnt[dir] = 0u;
            __threadfence();
            atomicAdd(&g_gen[dir], 1u);
        } else {
            while (atomicAdd(&g_gen[dir], 0u) == g0) { __nanosleep(64); }
        }
        __threadfence();
        *s_gen = g0 + 1u;
    }
    __syncthreads();
}

// grid = 256 CTAs (128 per direction, 2 per SM), 256 threads.
// Each CTA owns 4 h-columns (16 gate-cols) for all 32 batches.
// SMEM: W slice [512][16] (32KB) + h chunk [256][32] (32KB) + red 8x16x33.
__global__ __launch_bounds__(256,2) void lstm_layer_kernel(
    const float* __restrict__ Whh_f, const float* __restrict__ Whh_b, int layer)
{
    extern __shared__ float sm[];
    float* W_s  = sm;                    // [512][16]  = 8192 floats
    float* hp_s = sm + 8192;             // [256][32]  = 8192 floats (k-chunked)
    float* red  = sm + 16384;            // 8 splits x 16 cols x 33
    __shared__ unsigned s_gen;

    int dir = blockIdx.x >> 7;
    int cid = blockIdx.x & 127;
    int hc0 = cid * 4;
    int tid = threadIdx.x;
    const float* Whh = dir ? Whh_b : Whh_f;
    const float* xw  = g_xw[dir];
    float* outseq = layer ? g_seq1 : g_seq0;

    if (tid == 0) s_gen = g_gen[dir];

    // Load Whh slice transposed: W_s[k][q*4+j] = Whh[q*512 + hc0 + j][k]
    for (int idx = tid; idx < 512*16; idx += 256){
        int col = idx & 15, k = idx >> 4;
        int q = col >> 2, j = col & 3;
        W_s[k*16 + col] = Whh[(size_t)(q*512 + hc0 + j)*512 + k];
    }
    // Zero parity-0 h buffer for this CTA's 4 columns
    if (tid < 128){
        int j = tid >> 5, b = tid & 31;
        g_hT[(dir*2 + 0)*Hh*Bb + (hc0+j)*Bb + b] = 0.f;
    }
    float c_reg = 0.f;                   // tid<128: cell state for (hc0+jj, bb)
    int jj = (tid >> 5) & 3, bbn = tid & 31;

    int kg = tid >> 5;                   // 8 k-split groups (64 k each total)
    int t2 = tid & 31;
    int bq = (t2 & 7) * 4;               // batch quad
    int gq = (t2 >> 3) * 4;              // gate-col quad (0,4,8,12)

    // reduce-phase per-thread constants (2 outputs per thread)
    int colR[2], bIR[2], xoffR[2];
#pragma unroll
    for (int r = 0; r < 2; r++){
        int idx = tid + 256*r;
        colR[r] = idx >> 5;              // 0..15
        bIR[r]  = idx & 31;
        int q = colR[r] >> 2, j = colR[r] & 3;
        xoffR[r] = q*512 + hc0 + j;
    }

    grid_bar(dir, &s_gen);

    for (int t = 0; t < Ss; t++){
        int s = dir ? (Ss - 1 - t) : t;
        const float* xwt = xw + (size_t)s*Bb*Gg;

        // prefetch input-projection gate values (hidden behind matmul)
        float xpre[2];
#pragma unroll
        for (int r = 0; r < 2; r++)
            xpre[r] = __ldg(&xwt[(size_t)bIR[r]*Gg + xoffR[r]]);

        float acc[4][4];
#pragma unroll
        for (int i=0;i<4;i++)
#pragma unroll
            for (int j=0;j<4;j++) acc[i][j] = 0.f;

        const float4* hsrc4 = (const float4*)(g_hT + (dir*2 + (t & 1))*Hh*Bb);

#pragma unroll
        for (int chunk = 0; chunk < 2; chunk++){
            // stage 256-k chunk of h_prev (8 float4 per thread)
#pragma unroll
            for (int r = 0; r < 8; r++)
                ((float4*)hp_s)[tid + 256*r] = hsrc4[chunk*2048 + tid + 256*r];
            __syncthreads();

            const float* hpk = hp_s + kg*32*32;
            const float* wpk = W_s  + (chunk*256 + kg*32)*16;
#pragma unroll 8
            for (int k = 0; k < 32; k++){
                float4 hv = *reinterpret_cast<const float4*>(hpk + (k<<5) + bq);
                float4 wv = *reinterpret_cast<const float4*>(wpk + (k<<4) + gq);
                acc[0][0]=fmaf(wv.x,hv.x,acc[0][0]); acc[0][1]=fmaf(wv.x,hv.y,acc[0][1]);
                acc[0][2]=fmaf(wv.x,hv.z,acc[0][2]); acc[0][3]=fmaf(wv.x,hv.w,acc[0][3]);
                acc[1][0]=fmaf(wv.y,hv.x,acc[1][0]); acc[1][1]=fmaf(wv.y,hv.y,acc[1][1]);
                acc[1][2]=fmaf(wv.y,hv.z,acc[1][2]); acc[1][3]=fmaf(wv.y,hv.w,acc[1][3]);
                acc[2][0]=fmaf(wv.z,hv.x,acc[2][0]); acc[2][1]=fmaf(wv.z,hv.y,acc[2][1]);
                acc[2][2]=fmaf(wv.z,hv.z,acc[2][2]); acc[2][3]=fmaf(wv.z,hv.w,acc[2][3]);
                acc[3][0]=fmaf(wv.w,hv.x,acc[3][0]); acc[3][1]=fmaf(wv.w,hv.y,acc[3][1]);
                acc[3][2]=fmaf(wv.w,hv.z,acc[3][2]); acc[3][3]=fmaf(wv.w,hv.w,acc[3][3]);
            }
            __syncthreads();   // protect hp_s before restage / red reuse
        }

#pragma unroll
        for (int gi=0; gi<4; gi++)
#pragma unroll
            for (int bi=0; bi<4; bi++)
                red[kg*528 + (gq+gi)*33 + (bq+bi)] = acc[gi][bi];
        __syncthreads();

        // reduce 8 k-splits + add prefetched input projection
#pragma unroll
        for (int r = 0; r < 2; r++){
            int col = colR[r], bI = bIR[r];
            float v = xpre[r];
#pragma unroll
            for (int g = 0; g < 8; g++)
                v += red[g*528 + col*33 + bI];
            red[col*33 + bI] = v;
        }
        __syncthreads();

        // activations + state update (col = q*4 + j : i=jj, f=4+jj, g=8+jj, o=12+jj)
        if (tid < 128){
            float iv = red[( 0 + jj)*33 + bbn];
            float fv = red[( 4 + jj)*33 + bbn];
            float gv = red[( 8 + jj)*33 + bbn];
            float ov = red[(12 + jj)*33 + bbn];
            float cnew = sigf(fv)*c_reg + sigf(iv)*tanhf(gv);
            float hnew = sigf(ov)*tanhf(cnew);
            c_reg = cnew;
            g_hT[(dir*2 + ((t+1)&1))*Hh*Bb + (hc0+jj)*Bb + bbn] = hnew;
            outseq[((size_t)s*Bb + bbn)*1024 + dir*512 + hc0 + jj] = hnew;
        }

        grid_bar(dir, &s_gen);
    }
}

// ---------------- output projection [8192,1024] x [1024,30] ------------------
__global__ void out_proj_kernel(const float* __restrict__ Wout,
                                const float* __restrict__ bout,
                                float* __restrict__ out)
{
    int gw = (blockIdx.x*blockDim.x + threadIdx.x) >> 5;   // one warp per (s,b)
    int lane = threadIdx.x & 31;
    if (gw >= SB) return;
    const float* row = g_seq1 + (size_t)gw*1024;
    float xv[32];
#pragma unroll
    for (int i=0;i<32;i++) xv[i] = row[lane + 32*i];
    int s = gw >> 5, b = gw & 31;
    float* orow = out + ((size_t)b*Ss + s)*Cc;
    for (int c = 0; c < Cc; c++){
        const float* w = Wout + c*1024;
        float acc = 0.f;
#pragma unroll
        for (int i=0;i<32;i++) acc = fmaf(xv[i], w[lane + 32*i], acc);
#pragma unroll
        for (int off=16; off; off>>=1) acc += __shfl_xor_sync(0xffffffffu, acc, off);
        if (lane == 0) orow[c] = acc + bout[c];
    }
}

// ---------------- launch ------------------------------------------------------
extern "C" void kernel_launch(void* const* d_in, const int* in_sizes, int n_in,
                              void* d_out, int out_size)
{
    const float* hs     = (const float*)d_in[0];
    const int*   roles  = (const int*)  d_in[1];
    const int*   preds  = (const int*)  d_in[2];
    const float* Wih0f  = (const float*)d_in[3];
    const float* Whh0f  = (const float*)d_in[4];
    const float* bih0f  = (const float*)d_in[5];
    const float* bhh0f  = (const float*)d_in[6];
    const float* Wih0b  = (const float*)d_in[7];
    const float* Whh0b  = (const float*)d_in[8];
    const float* bih0b  = (const float*)d_in[9];
    const float* bhh0b  = (const float*)d_in[10];
    const float* Wih1f  = (const float*)d_in[11];
    const float* Whh1f  = (const float*)d_in[12];
    const float* bih1f  = (const float*)d_in[13];
    const float* bhh1f  = (const float*)d_in[14];
    const float* Wih1b  = (const float*)d_in[15];
    const float* Whh1b  = (const float*)d_in[16];
    const float* bih1b  = (const float*)d_in[17];
    const float* bhh1b  = (const float*)d_in[18];
    const float* Wout   = (const float*)d_in[19];
    const float* bout   = (const float*)d_in[20];
    float* out = (float*)d_out;

    const size_t lsm = (8192 + 8192 + 8*528) * sizeof(float);   // 82432
    cudaFuncSetAttribute(lstm_layer_kernel,
                         cudaFuncAttributeMaxDynamicSharedMemorySize, (int)lsm);

    feat_mean_kernel<<<SB, 256>>>(hs);
    pred_kernel<<<1, 32>>>(preds);
    fill_kernel<<<(Bb*Ss + 255)/256, 256>>>(roles);

    dim3 gproj(Gg/128, SB/128);
    sgemm_bias<<<gproj, 256>>>(0, Wih0f, bih0f, bhh0f, 0, IN0v);
    sgemm_bias<<<gproj, 256>>>(0, Wih0b, bih0b, bhh0b, 1, IN0v);
    lstm_layer_kernel<<<256, 256, lsm>>>(Whh0f, Whh0b, 0);

    sgemm_bias<<<gproj, 256>>>(1, Wih1f, bih1f, bhh1f, 0, 1024);
    sgemm_bias<<<gproj, 256>>>(1, Wih1b, bih1b, bhh1b, 1, 1024);
    lstm_layer_kernel<<<256, 256, lsm>>>(Whh1f, Whh1b, 1);

    out_proj_kernel<<<(SB*32 + 255)/256, 256>>>(Wout, bout, out);
}

// round 11
// speedup vs baseline: 2.1356x; 1.4412x over previous
#include <cuda_runtime.h>
#include <cuda_bf16.h>
#include <math.h>
#include <stdint.h>

#define Bb   32
#define Ss   256
#define Ee   768
#define Hh   512
#define Cc   30
#define IN0v 770
#define Gg   2048
#define SB   (Ss*Bb)          /* 8192 */
#define LSTRIDE (Bb*Ss*Ee)    /* hidden_states layer stride */
#define NCTA_DIR 128

// ---------------- scratch (device globals; no runtime allocation) ------------
__device__ float g_x0[SB*IN0v];        // [S][B][770]  layer-0 input features
__device__ float g_xw[2][SB*Gg];       // [dir][S][B][2048] precomputed input proj
__device__ float g_seq0[SB*1024];      // [S][B][1024] layer-0 output
__device__ float g_seq1[SB*1024];      // [S][B][1024] layer-1 output
__device__ float g_hT[2*2*Hh*Bb];      // [dir][parity][h][b] double-buffered h
__device__ float g_mw[Bb*Ss];          // mean over E per (b,s)
__device__ float g_mp[Bb];             // mean at predicate position per b
__device__ unsigned g_cnt[2];          // per-direction barrier arrive count
__device__ unsigned g_gen[2];          // per-direction barrier generation
// bf16 hi/lo staging for tensor-core GEMMs (Kp <= 1024)
__device__ __nv_bfloat16 g_Ah[SB*1024];
__device__ __nv_bfloat16 g_Al[SB*1024];
__device__ __nv_bfloat16 g_Wh[2][Gg*1024];
__device__ __nv_bfloat16 g_Wl[2][Gg*1024];

// ---------------- feature build ----------------------------------------------
__global__ void feat_mean_kernel(const float* __restrict__ hs)
{
    int bs = blockIdx.x;              // b*Ss + s
    int b = bs / Ss, s = bs % Ss;
    const float* p = hs + ((size_t)b*Ss + s)*Ee;
    size_t xb = ((size_t)s*Bb + b)*IN0v;
    float lsum = 0.f;
    for (int e = threadIdx.x; e < Ee; e += 256){
        float v = (p[e] + p[e+LSTRIDE] + p[e+2*LSTRIDE] + p[e+3*LSTRIDE])*0.25f;
        g_x0[xb + e] = v;
        lsum += v;
    }
    __shared__ float sred[256];
    sred[threadIdx.x] = lsum;
    __syncthreads();
    for (int st = 128; st > 0; st >>= 1){
        if (threadIdx.x < st) sred[threadIdx.x] += sred[threadIdx.x + st];
        __syncthreads();
    }
    if (threadIdx.x == 0) g_mw[bs] = sred[0]*(1.f/768.f);
}

__global__ void pred_kernel(const int* __restrict__ pred)
{
    int b = threadIdx.x;
    if (b >= Bb) return;
    const int* row = pred + b*Ss;
    int best = row[0], idx = 0;
    for (int s = 1; s < Ss; s++){ int v = row[s]; if (v > best){ best = v; idx = s; } }
    g_mp[b] = g_mw[b*Ss + idx];
}

__global__ void fill_kernel(const int* __restrict__ roles)
{
    int t = blockIdx.x*blockDim.x + threadIdx.x;
    if (t >= Bb*Ss) return;
    int b = t / Ss, s = t % Ss;
    int r = roles[t];
    size_t xb = ((size_t)s*Bb + b)*IN0v;
    g_x0[xb + Ee]     = g_mw[t] - g_mp[b];
    g_x0[xb + Ee + 1] = (r != 0 && r != -100) ? 1.f : 0.f;
}

// ---------------- bf16 hi/lo conversion ---------------------------------------
__global__ void convA_kernel(int srcSel, int K, int Kp)
{
    const float* A = srcSel ? g_seq0 : g_x0;
    int idx = blockIdx.x*256 + threadIdx.x;
    if (idx >= SB*Kp) return;
    int m = idx / Kp, k = idx - m*Kp;
    float v = (k < K) ? A[(size_t)m*K + k] : 0.f;
    __nv_bfloat16 h = __float2bfloat16(v);
    g_Ah[idx] = h;
    g_Al[idx] = __float2bfloat16(v - __bfloat162float(h));
}

__global__ void convW_kernel(const float* __restrict__ W, int K, int Kp, int dir)
{
    int idx = blockIdx.x*256 + threadIdx.x;
    if (idx >= Gg*Kp) return;
    int n = idx / Kp, k = idx - n*Kp;
    float v = (k < K) ? W[(size_t)n*K + k] : 0.f;
    __nv_bfloat16 h = __float2bfloat16(v);
    g_Wh[dir][idx] = h;
    g_Wl[dir][idx] = __float2bfloat16(v - __bfloat162float(h));
}

// ---------------- tensor-core GEMM  C = A*W^T + (b1+b2),  bf16x3 --------------
// A(hi/lo): [8192][Kp] bf16, W(hi/lo): [2048][Kp] bf16.  Tile 128x128, BK=16.
// 8 warps; warp (w&1,w>>1) owns 64m x 32n = 4x4 m16n8k16 sub-tiles.
#define MMA16816(C, A0,A1,A2,A3, B0,B1) \
    asm volatile("mma.sync.aligned.m16n8k16.row.col.f32.bf16.bf16.f32 " \
        "{%0,%1,%2,%3}, {%4,%5,%6,%7}, {%8,%9}, {%0,%1,%2,%3};" \
        : "+f"((C)[0]),"+f"((C)[1]),"+f"((C)[2]),"+f"((C)[3]) \
        : "r"(A0),"r"(A1),"r"(A2),"r"(A3),"r"(B0),"r"(B1))

__global__ __launch_bounds__(256,2) void tc_gemm_bias(
    int dir, const float* __restrict__ b1, const float* __restrict__ b2, int Kp)
{
    __shared__ uint32_t Ah_s[128][8], Al_s[128][8];
    __shared__ uint32_t Wh_s[128][8], Wl_s[128][8];

    float* Cmat = g_xw[dir];
    const __nv_bfloat16* Whg = g_Wh[dir];
    const __nv_bfloat16* Wlg = g_Wl[dir];

    int m0 = blockIdx.y*128, n0 = blockIdx.x*128;
    int tid = threadIdx.x;
    int lane = tid & 31, wid = tid >> 5;
    int g = lane >> 2, tg = lane & 3;
    int m_w = (wid & 1)*64, n_w = (wid >> 1)*32;

    int lrow = tid >> 1, lhw = tid & 1;   // loader: row, 16B-half

    float c[4][4][4];
#pragma unroll
    for (int mi=0;mi<4;mi++)
#pragma unroll
        for (int ni=0;ni<4;ni++)
#pragma unroll
            for (int q=0;q<4;q++) c[mi][ni][q] = 0.f;

    int steps = Kp >> 4;
    for (int s = 0; s < steps; s++){
        // ---- stage tiles (each thread: one uint4 = 8 bf16 per tile) ----
        size_t aoff = (size_t)(m0 + lrow)*Kp + s*16;
        size_t woff = (size_t)(n0 + lrow)*Kp + s*16;
        *(uint4*)&Ah_s[lrow][lhw*4] = ((const uint4*)(g_Ah + aoff))[lhw];
        *(uint4*)&Al_s[lrow][lhw*4] = ((const uint4*)(g_Al + aoff))[lhw];
        *(uint4*)&Wh_s[lrow][lhw*4] = ((const uint4*)(Whg  + woff))[lhw];
        *(uint4*)&Wl_s[lrow][lhw*4] = ((const uint4*)(Wlg  + woff))[lhw];
        __syncthreads();

        // ---- A fragments for all 4 m-subtiles (hi[0..3], lo[4..7]) ----
        uint32_t af[4][8];
#pragma unroll
        for (int mi=0;mi<4;mi++){
            int r0 = m_w + mi*16 + g;
            af[mi][0] = Ah_s[r0  ][tg];   af[mi][1] = Ah_s[r0+8][tg];
            af[mi][2] = Ah_s[r0  ][tg+4]; af[mi][3] = Ah_s[r0+8][tg+4];
            af[mi][4] = Al_s[r0  ][tg];   af[mi][5] = Al_s[r0+8][tg];
            af[mi][6] = Al_s[r0  ][tg+4]; af[mi][7] = Al_s[r0+8][tg+4];
        }

#pragma unroll
        for (int ni=0;ni<4;ni++){
            int rn = n_w + ni*8 + g;
            uint32_t bh0 = Wh_s[rn][tg], bh1 = Wh_s[rn][tg+4];
            uint32_t bl0 = Wl_s[rn][tg], bl1 = Wl_s[rn][tg+4];
#pragma unroll
            for (int mi=0;mi<4;mi++){
                MMA16816(c[mi][ni], af[mi][0],af[mi][1],af[mi][2],af[mi][3], bh0,bh1);
                MMA16816(c[mi][ni], af[mi][0],af[mi][1],af[mi][2],af[mi][3], bl0,bl1);
                MMA16816(c[mi][ni], af[mi][4],af[mi][5],af[mi][6],af[mi][7], bh0,bh1);
            }
        }
        __syncthreads();
    }

    // ---- epilogue: bias + store ----
#pragma unroll
    for (int mi=0;mi<4;mi++){
#pragma unroll
        for (int ni=0;ni<4;ni++){
            int m = m0 + m_w + mi*16 + g;
            int n = n0 + n_w + ni*8 + tg*2;
            float bb0 = b1[n] + b2[n];
            float bb1 = b1[n+1] + b2[n+1];
            float2 v0 = { c[mi][ni][0] + bb0, c[mi][ni][1] + bb1 };
            float2 v1 = { c[mi][ni][2] + bb0, c[mi][ni][3] + bb1 };
            *(float2*)&Cmat[(size_t)m*Gg + n]     = v0;
            *(float2*)&Cmat[(size_t)(m+8)*Gg + n] = v1;
        }
    }
}

// ---------------- persistent bidirectional LSTM layer ------------------------
// (byte-identical to R10-passing version)
__device__ __forceinline__ float sigf(float x){ return 1.f/(1.f + expf(-x)); }

__device__ __forceinline__ void grid_bar(int dir, unsigned* s_gen)
{
    __syncthreads();
    if (threadIdx.x == 0){
        __threadfence();
        unsigned g0 = *s_gen;
        if (atomicAdd(&g_cnt[dir], 1u) == NCTA_DIR - 1u){
            g_cnt[dir] = 0u;
            __threadfence();
            atomicAdd(&g_gen[dir], 1u);
        } else {
            while (atomicAdd(&g_gen[dir], 0u) == g0) { __nanosleep(64); }
        }
        __threadfence();
        *s_gen = g0 + 1u;
    }
    __syncthreads();
}

__global__ __launch_bounds__(256,2) void lstm_layer_kernel(
    const float* __restrict__ Whh_f, const float* __restrict__ Whh_b, int layer)
{
    extern __shared__ float sm[];
    float* W_s  = sm;                    // [512][16]  = 8192 floats
    float* hp_s = sm + 8192;             // [256][32]  = 8192 floats (k-chunked)
    float* red  = sm + 16384;            // 8 splits x 16 cols x 33
    __shared__ unsigned s_gen;

    int dir = blockIdx.x >> 7;
    int cid = blockIdx.x & 127;
    int hc0 = cid * 4;
    int tid = threadIdx.x;
    const float* Whh = dir ? Whh_b : Whh_f;
    const float* xw  = g_xw[dir];
    float* outseq = layer ? g_seq1 : g_seq0;

    if (tid == 0) s_gen = g_gen[dir];

    for (int idx = tid; idx < 512*16; idx += 256){
        int col = idx & 15, k = idx >> 4;
        int q = col >> 2, j = col & 3;
        W_s[k*16 + col] = Whh[(size_t)(q*512 + hc0 + j)*512 + k];
    }
    if (tid < 128){
        int j = tid >> 5, b = tid & 31;
        g_hT[(dir*2 + 0)*Hh*Bb + (hc0+j)*Bb + b] = 0.f;
    }
    float c_reg = 0.f;
    int jj = (tid >> 5) & 3, bbn = tid & 31;

    int kg = tid >> 5;
    int t2 = tid & 31;
    int bq = (t2 & 7) * 4;
    int gq = (t2 >> 3) * 4;

    int colR[2], bIR[2], xoffR[2];
#pragma unroll
    for (int r = 0; r < 2; r++){
        int idx = tid + 256*r;
        colR[r] = idx >> 5;
        bIR[r]  = idx & 31;
        int q = colR[r] >> 2, j = colR[r] & 3;
        xoffR[r] = q*512 + hc0 + j;
    }

    grid_bar(dir, &s_gen);

    for (int t = 0; t < Ss; t++){
        int s = dir ? (Ss - 1 - t) : t;
        const float* xwt = xw + (size_t)s*Bb*Gg;

        float xpre[2];
#pragma unroll
        for (int r = 0; r < 2; r++)
            xpre[r] = __ldg(&xwt[(size_t)bIR[r]*Gg + xoffR[r]]);

        float acc[4][4];
#pragma unroll
        for (int i=0;i<4;i++)
#pragma unroll
            for (int j=0;j<4;j++) acc[i][j] = 0.f;

        const float4* hsrc4 = (const float4*)(g_hT + (dir*2 + (t & 1))*Hh*Bb);

#pragma unroll
        for (int chunk = 0; chunk < 2; chunk++){
#pragma unroll
            for (int r = 0; r < 8; r++)
                ((float4*)hp_s)[tid + 256*r] = hsrc4[chunk*2048 + tid + 256*r];
            __syncthreads();

            const float* hpk = hp_s + kg*32*32;
            const float* wpk = W_s  + (chunk*256 + kg*32)*16;
#pragma unroll 8
            for (int k = 0; k < 32; k++){
                float4 hv = *reinterpret_cast<const float4*>(hpk + (k<<5) + bq);
                float4 wv = *reinterpret_cast<const float4*>(wpk + (k<<4) + gq);
                acc[0][0]=fmaf(wv.x,hv.x,acc[0][0]); acc[0][1]=fmaf(wv.x,hv.y,acc[0][1]);
                acc[0][2]=fmaf(wv.x,hv.z,acc[0][2]); acc[0][3]=fmaf(wv.x,hv.w,acc[0][3]);
                acc[1][0]=fmaf(wv.y,hv.x,acc[1][0]); acc[1][1]=fmaf(wv.y,hv.y,acc[1][1]);
                acc[1][2]=fmaf(wv.y,hv.z,acc[1][2]); acc[1][3]=fmaf(wv.y,hv.w,acc[1][3]);
                acc[2][0]=fmaf(wv.z,hv.x,acc[2][0]); acc[2][1]=fmaf(wv.z,hv.y,acc[2][1]);
                acc[2][2]=fmaf(wv.z,hv.z,acc[2][2]); acc[2][3]=fmaf(wv.z,hv.w,acc[2][3]);
                acc[3][0]=fmaf(wv.w,hv.x,acc[3][0]); acc[3][1]=fmaf(wv.w,hv.y,acc[3][1]);
                acc[3][2]=fmaf(wv.w,hv.z,acc[3][2]); acc[3][3]=fmaf(wv.w,hv.w,acc[3][3]);
            }
            __syncthreads();
        }

#pragma unroll
        for (int gi=0; gi<4; gi++)
#pragma unroll
            for (int bi=0; bi<4; bi++)
                red[kg*528 + (gq+gi)*33 + (bq+bi)] = acc[gi][bi];
        __syncthreads();

#pragma unroll
        for (int r = 0; r < 2; r++){
            int col = colR[r], bI = bIR[r];
            float v = xpre[r];
#pragma unroll
            for (int g2 = 0; g2 < 8; g2++)
                v += red[g2*528 + col*33 + bI];
            red[col*33 + bI] = v;
        }
        __syncthreads();

        if (tid < 128){
            float iv = red[( 0 + jj)*33 + bbn];
            float fv = red[( 4 + jj)*33 + bbn];
            float gv = red[( 8 + jj)*33 + bbn];
            float ov = red[(12 + jj)*33 + bbn];
            float cnew = sigf(fv)*c_reg + sigf(iv)*tanhf(gv);
            float hnew = sigf(ov)*tanhf(cnew);
            c_reg = cnew;
            g_hT[(dir*2 + ((t+1)&1))*Hh*Bb + (hc0+jj)*Bb + bbn] = hnew;
            outseq[((size_t)s*Bb + bbn)*1024 + dir*512 + hc0 + jj] = hnew;
        }

        grid_bar(dir, &s_gen);
    }
}

// ---------------- output projection [8192,1024] x [1024,30] ------------------
__global__ void out_proj_kernel(const float* __restrict__ Wout,
                                const float* __restrict__ bout,
                                float* __restrict__ out)
{
    int gw = (blockIdx.x*blockDim.x + threadIdx.x) >> 5;
    int lane = threadIdx.x & 31;
    if (gw >= SB) return;
    const float* row = g_seq1 + (size_t)gw*1024;
    float xv[32];
#pragma unroll
    for (int i=0;i<32;i++) xv[i] = row[lane + 32*i];
    int s = gw >> 5, b = gw & 31;
    float* orow = out + ((size_t)b*Ss + s)*Cc;
    for (int c = 0; c < Cc; c++){
        const float* w = Wout + c*1024;
        float acc = 0.f;
#pragma unroll
        for (int i=0;i<32;i++) acc = fmaf(xv[i], w[lane + 32*i], acc);
#pragma unroll
        for (int off=16; off; off>>=1) acc += __shfl_xor_sync(0xffffffffu, acc, off);
        if (lane == 0) orow[c] = acc + bout[c];
    }
}

// ---------------- launch ------------------------------------------------------
extern "C" void kernel_launch(void* const* d_in, const int* in_sizes, int n_in,
                              void* d_out, int out_size)
{
    const float* hs     = (const float*)d_in[0];
    const int*   roles  = (const int*)  d_in[1];
    const int*   preds  = (const int*)  d_in[2];
    const float* Wih0f  = (const float*)d_in[3];
    const float* Whh0f  = (const float*)d_in[4];
    const float* bih0f  = (const float*)d_in[5];
    const float* bhh0f  = (const float*)d_in[6];
    const float* Wih0b  = (const float*)d_in[7];
    const float* Whh0b  = (const float*)d_in[8];
    const float* bih0b  = (const float*)d_in[9];
    const float* bhh0b  = (const float*)d_in[10];
    const float* Wih1f  = (const float*)d_in[11];
    const float* Whh1f  = (const float*)d_in[12];
    const float* bih1f  = (const float*)d_in[13];
    const float* bhh1f  = (const float*)d_in[14];
    const float* Wih1b  = (const float*)d_in[15];
    const float* Whh1b  = (const float*)d_in[16];
    const float* bih1b  = (const float*)d_in[17];
    const float* bhh1b  = (const float*)d_in[18];
    const float* Wout   = (const float*)d_in[19];
    const float* bout   = (const float*)d_in[20];
    float* out = (float*)d_out;

    const size_t lsm = (8192 + 8192 + 8*528) * sizeof(float);   // 82432
    cudaFuncSetAttribute(lstm_layer_kernel,
                         cudaFuncAttributeMaxDynamicSharedMemorySize, (int)lsm);

    feat_mean_kernel<<<SB, 256>>>(hs);
    pred_kernel<<<1, 32>>>(preds);
    fill_kernel<<<(Bb*Ss + 255)/256, 256>>>(roles);

    dim3 gproj(Gg/128, SB/128);   // (16, 64)

    // ---- layer 0: Kp = 784 ----
    {
        const int K = IN0v, Kp = 784;
        convA_kernel<<<(SB*Kp + 255)/256, 256>>>(0, K, Kp);
        convW_kernel<<<(Gg*Kp + 255)/256, 256>>>(Wih0f, K, Kp, 0);
        convW_kernel<<<(Gg*Kp + 255)/256, 256>>>(Wih0b, K, Kp, 1);
        tc_gemm_bias<<<gproj, 256>>>(0, bih0f, bhh0f, Kp);
        tc_gemm_bias<<<gproj, 256>>>(1, bih0b, bhh0b, Kp);
    }
    lstm_layer_kernel<<<256, 256, lsm>>>(Whh0f, Whh0b, 0);

    // ---- layer 1: Kp = 1024 ----
    {
        const int K = 1024, Kp = 1024;
        convA_kernel<<<(SB*Kp + 255)/256, 256>>>(1, K, Kp);
        convW_kernel<<<(Gg*Kp + 255)/256, 256>>>(Wih1f, K, Kp, 0);
        convW_kernel<<<(Gg*Kp + 255)/256, 256>>>(Wih1b, K, Kp, 1);
        tc_gemm_bias<<<gproj, 256>>>(0, bih1f, bhh1f, Kp);
        tc_gemm_bias<<<gproj, 256>>>(1, bih1b, bhh1b, Kp);
    }
    lstm_layer_kernel<<<256, 256, lsm>>>(Whh1f, Whh1b, 1);

    out_proj_kernel<<<(SB*32 + 255)/256, 256>>>(Wout, bout, out);
}